// round 15
// baseline (speedup 1.0000x reference)
#include <cuda_runtime.h>
#include <cuda_fp16.h>
#include <math.h>
#include <stdint.h>

// ---------------- problem constants ----------------
#define BSZ 8
#define SEQ 512
#define ROWS 4096          // BSZ*SEQ
#define SPATIAL 512
#define NF 257             // rfft bins
#define F2 514
#define F4 1028
#define FH 128
#define MAX_STEPS 20
#define TOLV 1e-3f
// padded GEMM dims
#define KW1 1088           // GEMM1 K: 2*544
#define NW1 2176
#define KW2 1056           // GEMM2 K
#define NW2 640
#define KD  544            // gating K / fp16 state row
#define NG  385            // gating N: 257 hd + 128 hs
#define NGP 512
#define NBASE 2176
// FFT split-fp16 GEMM dims
#define KFR 1536           // rfft K: 3*512
#define KFI 1632           // irfft K: 3*544
// GEMM smem: 4 stages x (A 128x40 + B 128x40) halfs
#define STAGE_H 10240
#define STAGE_B 20480
#define SMEM_BYTES (4 * STAGE_B)

// ---------------- device scratch (static, zero-initialized) ----------------
__device__ float g_ct[2 * ROWS * F2];      // fp32 state: rows 0..4095 c, 4096.. t
__device__ float g_new[2 * ROWS * F2];
__device__ float g_h[ROWS * 2056];         // merged GEMM1 output
__device__ float g_fct[2 * ROWS * F2];     // rows 0..4095 fc, 4096.. ft
__device__ float g_g[2 * ROWS * 512];      // gating hidden: cols 0..256 hd, 257..384 hs
__device__ float g_base[BSZ * NBASE];
__device__ float g_gbias[NGP];
__device__ float g_rn_c[ROWS], g_rn_t[ROWS], g_sq_c[ROWS], g_sq_t[ROWS];
__device__ float g_scal[4];
__device__ int   g_done;
// fp16 activations (pads never written -> stay zero)
__device__ __half g_ct_h[2 * ROWS * KD];
__device__ __half g_h_h[2 * ROWS * KW2];
// fp16 K-major weights (pads stay zero)
__device__ __half g_w1T[NW1 * KW1];
__device__ __half g_cw2T[NW2 * KW2];
__device__ __half g_tw2T[NW2 * KW2];
__device__ __half g_gwT[NGP * KD];
// split-fp16 FFT operands/tables
__device__ __half g_fftA[2 * ROWS * KFR];  // [x_hi | x_hi | x_lo]
__device__ __half g_irA[2 * ROWS * KFI];   // [s_hi | s_hi | s_lo]
__device__ __half g_BrT[640 * KFR];
__device__ __half g_BiT[512 * KFI];

// ---------------- helpers ----------------
__device__ __forceinline__ float gelu_f(float x) {
    return 0.5f * x * (1.0f + erff(x * 0.70710678118654752f));
}
__device__ __forceinline__ uint32_t smem_u32(const void* p) {
    uint32_t a;
    asm("{ .reg .u64 t; cvta.to.shared.u64 t, %1; cvt.u32.u64 %0, t; }" : "=r"(a) : "l"(p));
    return a;
}
__device__ __forceinline__ void cp16(uint32_t dst, const void* src) {
    asm volatile("cp.async.cg.shared.global [%0], [%1], 16;" :: "r"(dst), "l"(src));
}
__device__ __forceinline__ void ldm_x4(uint32_t* r, uint32_t addr) {
    asm volatile("ldmatrix.sync.aligned.m8n8.x4.shared.b16 {%0,%1,%2,%3}, [%4];"
                 : "=r"(r[0]), "=r"(r[1]), "=r"(r[2]), "=r"(r[3]) : "r"(addr));
}

// ---------------- table init: split-fp16 DFT tables ----------------
__global__ void k_init_tables() {
    int idx = blockIdx.x * blockDim.x + threadIdx.x;
    if (idx == 0) g_done = 0;
    int total = SPATIAL * NF;
    if (idx >= total) return;
    int n = idx / NF, q = idx % NF;
    double r = (double)((q * n) & 511) / 256.0;
    double sv, cv;
    sincospi(r, &sv, &cv);
    float cf = (float)cv, sf = (float)(-sv);
    __half chh = __float2half_rn(cf), shh = __float2half_rn(sf);
    __half cll = __float2half_rn(cf - __half2float(chh));
    __half sll = __float2half_rn(sf - __half2float(shh));
    __half* Rc = g_BrT + (size_t)(2 * q) * KFR;
    __half* Rs = g_BrT + (size_t)(2 * q + 1) * KFR;
    Rc[n] = chh; Rc[512 + n] = cll; Rc[1024 + n] = chh;
    Rs[n] = shh; Rs[512 + n] = sll; Rs[1024 + n] = shh;
    double w = (q == 0 || q == NF - 1) ? 1.0 : 2.0;
    float ic = (float)(w * cv / 512.0), is = (float)(-w * sv / 512.0);
    __half ich = __float2half_rn(ic), ish = __float2half_rn(is);
    __half icl = __float2half_rn(ic - __half2float(ich));
    __half isl = __float2half_rn(is - __half2float(ish));
    __half* Bn = g_BiT + (size_t)n * KFI;
    Bn[2 * q] = ich;        Bn[544 + 2 * q] = icl;        Bn[1088 + 2 * q] = ich;
    Bn[2 * q + 1] = ish;    Bn[544 + 2 * q + 1] = isl;    Bn[1088 + 2 * q + 1] = ish;
}

// ---------------- input split ----------------
__global__ void k_split_in(const float* __restrict__ carrier, const float* __restrict__ traj) {
    int r = blockIdx.x, tid = threadIdx.x;
    const float* src = (r < ROWS) ? carrier + (size_t)r * SPATIAL
                                  : traj + (size_t)(r - ROWS) * SPATIAL;
    __half* d = g_fftA + (size_t)r * KFR;
    for (int k = tid; k < SPATIAL; k += 256) {
        float x = src[k];
        __half h = __float2half_rn(x);
        __half l = __float2half_rn(x - __half2float(h));
        d[k] = h; d[512 + k] = h; d[1024 + k] = l;
    }
}

// ---------------- state split for irfft ----------------
__global__ void k_split_state() {
    int r = blockIdx.x, tid = threadIdx.x;
    const float* src = g_ct + (size_t)r * F2;
    __half* d = g_irA + (size_t)r * KFI;
    for (int j = tid; j < F2; j += 256) {
        float x = src[j];
        __half h = __float2half_rn(x);
        __half l = __float2half_rn(x - __half2float(h));
        d[j] = h; d[544 + j] = h; d[1088 + j] = l;
    }
}

// ---------------- transpose ----------------
__global__ void k_tr(const float* __restrict__ W, int K, int N,
                     __half* __restrict__ WT, int ldk, int n_off) {
    int k = blockIdx.x * 256 + threadIdx.x;
    int n = blockIdx.y;
    if (k >= K) return;
    WT[(size_t)(n_off + n) * ldk + k] = __float2half_rn(W[(size_t)k * N + n]);
}

// ---------------- gating bias concat ----------------
__global__ void k_gbias(const float* __restrict__ db1, const float* __restrict__ sb1) {
    int i = threadIdx.x + blockIdx.x * 256;
    if (i >= NGP) return;
    g_gbias[i] = (i < 257) ? db1[i] : (i < NG ? sb1[i - 257] : 0.f);
}

// =====================================================================
// FP16 tensor GEMM, 4-stage cp.async(16B) pipeline, ldmatrix fragments,
// one sync per K-block, 2 CTAs/SM.  (exact R10 kernel)
// =====================================================================
__global__ __launch_bounds__(256, 2) void k_gemm_h(
    const __half* __restrict__ A_lo, const __half* __restrict__ A_hi,
    int ldaH, int kb_lo,
    const __half* __restrict__ B_lo, const __half* __restrict__ B_hi,
    int ldbH, int M_lo,
    float* __restrict__ C, int ldc, int M, int N, int nkb,
    const float* __restrict__ bias_lo, const float* __restrict__ bias_hi,
    const float* __restrict__ base, int base_ld,
    __half* __restrict__ Ch, int ldch,
    int act, int chk) {
    if (chk && g_done) return;
    extern __shared__ __half dyn[];

    const int tid = threadIdx.x;
    const int warp = tid >> 5, lane = tid & 31;
    const int gid = lane >> 2, tg = lane & 3;
    const int wm = warp & 1, wn = warp >> 1;
    const int row0 = blockIdx.y * 128, col0 = blockIdx.x * 128;

    const __half* BT = (row0 < M_lo) ? B_lo : B_hi;
    const float* bias = (row0 < M_lo) ? bias_lo : bias_hi;

    float acc[4][4][4];
#pragma unroll
    for (int mi = 0; mi < 4; mi++)
#pragma unroll
        for (int ni = 0; ni < 4; ni++)
#pragma unroll
            for (int q = 0; q < 4; q++) acc[mi][ni][q] = 0.f;

    const uint32_t sbase = smem_u32(dyn);
    const int rr2 = tid >> 2;
    const int c16 = tid & 3;

    auto issue = [&](int kb) {
        int buf = kb & 3;
        const __half* Ab;
        int kk;
        if (kb < kb_lo) { Ab = A_lo; kk = kb * 32; }
        else            { Ab = A_hi; kk = (kb - kb_lo) * 32; }
        uint32_t dA = sbase + buf * STAGE_B + rr2 * 80u + c16 * 16u;
        const __half* gA = Ab + (size_t)(row0 + rr2) * ldaH + kk + c16 * 8;
        cp16(dA, gA);
        cp16(dA + 64 * 80u, gA + (size_t)64 * ldaH);
        uint32_t dB = dA + 10240u;
        const __half* gB = BT + (size_t)(col0 + rr2) * ldbH + kb * 32 + c16 * 8;
        cp16(dB, gB);
        cp16(dB + 64 * 80u, gB + (size_t)64 * ldbH);
        asm volatile("cp.async.commit_group;" ::: "memory");
    };
    auto commit_empty = [&]() {
        asm volatile("cp.async.commit_group;" ::: "memory");
    };

    const uint32_t aRow = (uint32_t)(wm * 64 + (lane & 7) + ((lane & 8) ? 8 : 0));
    const uint32_t aColB = (lane & 16) ? 16u : 0u;
    const uint32_t bRow = (uint32_t)(wn * 32 + (lane & 7) + ((lane & 16) ? 8 : 0));
    const uint32_t bColB = (lane & 8) ? 16u : 0u;

    issue(0);
    if (nkb > 1) issue(1); else commit_empty();

    for (int kb = 0; kb < nkb; kb++) {
        if (kb + 2 < nkb) issue(kb + 2); else commit_empty();
        asm volatile("cp.async.wait_group 2;" ::: "memory");
        __syncthreads();
        int buf = kb & 3;
        uint32_t stA = sbase + buf * STAGE_B;
        uint32_t stB = stA + 10240u;
#pragma unroll
        for (int s = 0; s < 2; s++) {
            uint32_t af[4][4], bf[4][2];
#pragma unroll
            for (int mi = 0; mi < 4; mi++)
                ldm_x4(af[mi], stA + (aRow + mi * 16) * 80u + s * 32u + aColB);
#pragma unroll
            for (int nj = 0; nj < 2; nj++) {
                uint32_t r[4];
                ldm_x4(r, stB + (bRow + nj * 16) * 80u + s * 32u + bColB);
                bf[2 * nj][0] = r[0]; bf[2 * nj][1] = r[1];
                bf[2 * nj + 1][0] = r[2]; bf[2 * nj + 1][1] = r[3];
            }
#pragma unroll
            for (int mi = 0; mi < 4; mi++)
#pragma unroll
                for (int ni = 0; ni < 4; ni++) {
                    asm volatile(
                        "mma.sync.aligned.m16n8k16.row.col.f32.f16.f16.f32 "
                        "{%0,%1,%2,%3}, {%4,%5,%6,%7}, {%8,%9}, {%0,%1,%2,%3};"
                        : "+f"(acc[mi][ni][0]), "+f"(acc[mi][ni][1]),
                          "+f"(acc[mi][ni][2]), "+f"(acc[mi][ni][3])
                        : "r"(af[mi][0]), "r"(af[mi][1]), "r"(af[mi][2]), "r"(af[mi][3]),
                          "r"(bf[ni][0]), "r"(bf[ni][1]));
                }
        }
    }

    // epilogue
#pragma unroll
    for (int mi = 0; mi < 4; mi++) {
#pragma unroll
        for (int ni = 0; ni < 4; ni++) {
#pragma unroll
            for (int q = 0; q < 4; q++) {
                int r = row0 + wm * 64 + mi * 16 + gid + (q >> 1) * 8;
                int c = col0 + wn * 32 + ni * 8 + tg * 2 + (q & 1);
                if (r >= M || c >= N) continue;
                float v = acc[mi][ni][q];
                if (bias) v += bias[c];
                if (base) v += base[(r >> 9) * base_ld + c];
                if (act == 1) v = gelu_f(v);
                else if (act == 2) v = tanhf(v);
                C[(size_t)r * ldc + c] = v;
                if (Ch) Ch[(size_t)r * ldch + c] = __float2half_rn(v);
            }
        }
    }
}

// ---------------- per-batch constant base ----------------
__global__ void k_base(const float* __restrict__ src, const float* __restrict__ tgt,
                       const float* __restrict__ w1, const float* __restrict__ b1,
                       int out_off) {
    int b = blockIdx.y;
    int tid = threadIdx.x;
    int jj = tid & 31;
    int ks = tid >> 5;
    int j = blockIdx.x * 32 + jj;
    float s = 0.f;
    if (j < F4) {
        const float* ps = src + b * 513;
        const float* pt = tgt + b * 513;
        for (int k = ks * 128; k < ks * 128 + 128; k++) {
            float x = (k < 512) ? ps[k] : pt[k - 512];
            s = fmaf(x, w1[(size_t)(F4 + k) * F4 + j], s);
        }
    }
    __shared__ float sh[8][32];
    sh[ks][jj] = s;
    __syncthreads();
    if (ks == 0 && j < F4) {
        float t = b1[j];
#pragma unroll
        for (int q = 0; q < 8; q++) t += sh[q][jj];
        g_base[b * NBASE + out_off + j] = t;
    }
}

// ---------------- LayerNorm + GELU -> fp16 hidden + GEMM2 tail cols ----------------
// also computes fct[row][512], fct[row][513] = tanh(y . w2T[512/513] + b2)
__global__ void k_ln_gelu(const float* __restrict__ gc, const float* __restrict__ bc,
                          const float* __restrict__ gt, const float* __restrict__ bt,
                          const float* __restrict__ cb2, const float* __restrict__ tb2) {
    if (g_done) return;
    int r = blockIdx.x, h = blockIdx.y, tid = threadIdx.x;
    const float* g = h ? gt : gc;
    const float* be = h ? bt : bc;
    const float* b2 = h ? tb2 : cb2;
    const __half* w512 = (h ? g_tw2T : g_cw2T) + (size_t)512 * KW2;
    const __half* w513 = (h ? g_tw2T : g_cw2T) + (size_t)513 * KW2;
    const float4* hr = (const float4*)(g_h + (size_t)r * 2056 + h * 1028);
    __half2* out = (__half2*)(g_h_h + (size_t)(h * ROWS + r) * KW2);
    float s = 0.f, s2 = 0.f;
    for (int j = tid; j < 257; j += 256) {
        float4 x = hr[j];
        s += x.x + x.y + x.z + x.w;
        s2 += x.x * x.x + x.y * x.y + x.z * x.z + x.w * x.w;
    }
    __shared__ float sa[256], sb[256];
    sa[tid] = s; sb[tid] = s2;
    __syncthreads();
    for (int o = 128; o > 0; o >>= 1) {
        if (tid < o) { sa[tid] += sa[tid + o]; sb[tid] += sb[tid + o]; }
        __syncthreads();
    }
    float mean = sa[0] / F4;
    float var = sb[0] / F4 - mean * mean;
    float rs = rsqrtf(var + 1e-5f);
    __syncthreads();   // protect sa/sb reuse below
    const float4* g4 = (const float4*)g;
    const float4* b4 = (const float4*)be;
    float d0 = 0.f, d1 = 0.f;
    for (int j = tid; j < 257; j += 256) {
        float4 x = hr[j], gg = g4[j], bb = b4[j];
        float y0 = gelu_f((x.x - mean) * rs * gg.x + bb.x);
        float y1 = gelu_f((x.y - mean) * rs * gg.y + bb.y);
        float y2 = gelu_f((x.z - mean) * rs * gg.z + bb.z);
        float y3 = gelu_f((x.w - mean) * rs * gg.w + bb.w);
        float2 lo = make_float2(y0, y1), hi = make_float2(y2, y3);
        out[2 * j] = __float22half2_rn(lo);
        out[2 * j + 1] = __float22half2_rn(hi);
        // tail dot products (weights fp16, broadcast-cached)
        int k4 = 4 * j;
        float2 wa = __half22float2(*(const __half2*)(w512 + k4));
        float2 wb = __half22float2(*(const __half2*)(w512 + k4 + 2));
        d0 = fmaf(y0, wa.x, fmaf(y1, wa.y, fmaf(y2, wb.x, fmaf(y3, wb.y, d0))));
        float2 va = __half22float2(*(const __half2*)(w513 + k4));
        float2 vb = __half22float2(*(const __half2*)(w513 + k4 + 2));
        d1 = fmaf(y0, va.x, fmaf(y1, va.y, fmaf(y2, vb.x, fmaf(y3, vb.y, d1))));
    }
    sa[tid] = d0; sb[tid] = d1;
    __syncthreads();
    for (int o = 128; o > 0; o >>= 1) {
        if (tid < o) { sa[tid] += sa[tid + o]; sb[tid] += sb[tid + o]; }
        __syncthreads();
    }
    if (tid == 0) {
        float* fct = g_fct + (size_t)(h * ROWS + r) * F2;
        fct[512] = tanhf(sa[0] + b2[512]);
        fct[513] = tanhf(sb[0] + b2[513]);
    }
}

// ---------------- fused heads + update (exact R10 version) ----------------
__global__ void k_gate_update(const float* __restrict__ fd,
                              const float* __restrict__ dw2, const float* __restrict__ db2,
                              const float* __restrict__ sw2, const float* __restrict__ sb2,
                              const float* __restrict__ cs_p, const float* __restrict__ ts_p) {
    if (g_done) return;
    int row = blockIdx.x, tid = threadIdx.x;
    const float* gc = g_g + (size_t)row * 512;
    const float* gt = g_g + (size_t)(ROWS + row) * 512;
    float s1 = 0.f, s2 = 0.f, s3 = 0.f;
    for (int k = tid; k < 257; k += 256) {
        float w = dw2[k];
        s1 = fmaf(gc[k], w, s1);
        s2 = fmaf(gt[k], w, s2);
    }
    if (tid < 128) s3 = gc[257 + tid] * sw2[tid];
    __shared__ float h1[256], h2[256], h3[256];
    h1[tid] = s1; h2[tid] = s2; h3[tid] = s3;
    __syncthreads();
    for (int o = 128; o > 0; o >>= 1) {
        if (tid < o) { h1[tid] += h1[tid + o]; h2[tid] += h2[tid + o]; h3[tid] += h3[tid + o]; }
        __syncthreads();
    }
    __shared__ float sh_ac, sh_at;
    if (tid == 0) {
        float a_c = 1.f / (1.f + expf(-(h1[0] + db2[0])));
        float a_t = 1.f / (1.f + expf(-(h2[0] + db2[0])));
        if (isnan(a_c)) a_c = 0.f;
        if (isnan(a_t)) a_t = 0.f;
        float gam = 1.f / (1.f + expf(-(h3[0] + sb2[0]))) + 0.5f;
        sh_ac = gam * a_c * (*cs_p);
        sh_at = gam * a_t * (*ts_p);
    }
    __syncthreads();
    float ac = sh_ac, at = sh_at;

    const float2* ct_c = (const float2*)(g_ct + (size_t)row * F2);
    const float2* ct_t = (const float2*)(g_ct + (size_t)(ROWS + row) * F2);
    const float2* fc2 = (const float2*)(g_fct + (size_t)row * F2);
    const float2* ft2 = (const float2*)(g_fct + (size_t)(ROWS + row) * F2);
    float2* nw_c = (float2*)(g_new + (size_t)row * F2);
    float2* nw_t = (float2*)(g_new + (size_t)(ROWS + row) * F2);
    float dc2 = 0.f, dt2 = 0.f, sc2 = 0.f, st2 = 0.f;
    for (int j2 = tid; j2 < 257; j2 += 256) {
        int j = 2 * j2;
        float fd0 = fd[j < NF ? j : j - NF];
        float fd1 = fd[(j + 1) < NF ? (j + 1) : (j + 1 - NF)];
        float2 c = ct_c[j2], f = fc2[j2];
        float2 nc;
        nc.x = fmaf(fd0, c.x, ac * f.x);
        nc.y = fmaf(fd1, c.y, ac * f.y);
        nw_c[j2] = nc;
        float d0 = nc.x - c.x, d1 = nc.y - c.y;
        dc2 += d0 * d0 + d1 * d1; sc2 += nc.x * nc.x + nc.y * nc.y;
        float2 t = ct_t[j2], ff = ft2[j2];
        float2 nt;
        nt.x = fmaf(fd0, t.x, at * ff.x);
        nt.y = fmaf(fd1, t.y, at * ff.y);
        nw_t[j2] = nt;
        d0 = nt.x - t.x; d1 = nt.y - t.y;
        dt2 += d0 * d0 + d1 * d1; st2 += nt.x * nt.x + nt.y * nt.y;
    }
    h1[tid] = dc2; h2[tid] = dt2; h3[tid] = sc2;
    __shared__ float h4[256];
    h4[tid] = st2;
    __syncthreads();
    for (int o = 128; o > 0; o >>= 1) {
        if (tid < o) { h1[tid] += h1[tid + o]; h2[tid] += h2[tid + o];
                       h3[tid] += h3[tid + o]; h4[tid] += h4[tid + o]; }
        __syncthreads();
    }
    if (tid == 0) {
        g_rn_c[row] = sqrtf(h1[0]);
        g_rn_t[row] = sqrtf(h2[0]);
        g_sq_c[row] = h3[0];
        g_sq_t[row] = h4[0];
    }
}

// ---------------- reduce + convergence decision ----------------
__global__ void k_reduce_finalize() {
    __shared__ float4 sh[1024];
    int tid = threadIdx.x;
    float4 a = make_float4(0.f, 0.f, 0.f, 0.f);
    for (int i = tid; i < ROWS; i += 1024) {
        a.x += g_rn_c[i]; a.y += g_rn_t[i]; a.z += g_sq_c[i]; a.w += g_sq_t[i];
    }
    sh[tid] = a;
    __syncthreads();
    for (int o = 512; o > 0; o >>= 1) {
        if (tid < o) {
            sh[tid].x += sh[tid + o].x; sh[tid].y += sh[tid + o].y;
            sh[tid].z += sh[tid + o].z; sh[tid].w += sh[tid + o].w;
        }
        __syncthreads();
    }
    if (tid == 0) {
        if (g_done) {
            g_scal[2] = 0.f;
        } else {
            float dc = sh[0].x / (float)ROWS;
            float dt = sh[0].y / (float)ROWS;
            float nc = sqrtf(sh[0].z);
            float nt = sqrtf(sh[0].w);
            int conv = (dc < TOLV) && (dt < TOLV);
            g_scal[0] = conv ? 1.f : (nc > 10.f ? 10.f / nc : 1.f);
            g_scal[1] = conv ? 1.f : (nt > 10.f ? 10.f / nt : 1.f);
            g_scal[2] = 1.f;
            if (conv) g_done = 1;
        }
    }
}

// ---------------- apply: commit state (fp32 + fp16) ----------------
__global__ void k_apply() {
    if (g_scal[2] == 0.f) return;
    int r = blockIdx.x, tid = threadIdx.x;
    float sc = (r < ROWS) ? g_scal[0] : g_scal[1];
    const float2* nw = (const float2*)(g_new + (size_t)r * F2);
    float2* ct = (float2*)(g_ct + (size_t)r * F2);
    __half2* hh = (__half2*)(g_ct_h + (size_t)r * KD);
    for (int j = tid; j < 257; j += 256) {
        float2 v = nw[j];
        v.x *= sc; v.y *= sc;
        ct[j] = v;
        hh[j] = __float22half2_rn(v);
    }
}

// ---------------- host launch ----------------
extern "C" void kernel_launch(void* const* d_in, const int* in_sizes, int n_in,
                              void* d_out, int out_size) {
    const float* carrier = (const float*)d_in[0];
    const float* traj    = (const float*)d_in[1];
    const float* srcp    = (const float*)d_in[2];
    const float* tgtp    = (const float*)d_in[3];
    const float* cw1 = (const float*)d_in[4];
    const float* cb1 = (const float*)d_in[5];
    const float* cg  = (const float*)d_in[6];
    const float* cbe = (const float*)d_in[7];
    const float* cw2 = (const float*)d_in[8];
    const float* cb2 = (const float*)d_in[9];
    const float* tw1 = (const float*)d_in[10];
    const float* tb1 = (const float*)d_in[11];
    const float* tg_ = (const float*)d_in[12];
    const float* tbe = (const float*)d_in[13];
    const float* tw2 = (const float*)d_in[14];
    const float* tb2 = (const float*)d_in[15];
    const float* fd  = (const float*)d_in[16];
    const float* dw1 = (const float*)d_in[17];
    const float* db1 = (const float*)d_in[18];
    const float* dw2 = (const float*)d_in[19];
    const float* db2 = (const float*)d_in[20];
    const float* sw1 = (const float*)d_in[21];
    const float* sb1 = (const float*)d_in[22];
    const float* sw2 = (const float*)d_in[23];
    const float* sb2 = (const float*)d_in[24];
    const float* csc = (const float*)d_in[25];
    const float* tsc = (const float*)d_in[26];
    float* out = (float*)d_out;

    float *p_ct, *p_h, *p_fct, *p_g, *p_base, *p_gbias;
    __half *p_ct_h, *p_h_h, *p_w1T, *p_cw2T, *p_tw2T, *p_gwT;
    __half *p_fftA, *p_irA, *p_BrT, *p_BiT;
    cudaGetSymbolAddress((void**)&p_ct,   g_ct);
    cudaGetSymbolAddress((void**)&p_h,    g_h);
    cudaGetSymbolAddress((void**)&p_fct,  g_fct);
    cudaGetSymbolAddress((void**)&p_g,    g_g);
    cudaGetSymbolAddress((void**)&p_base, g_base);
    cudaGetSymbolAddress((void**)&p_gbias,g_gbias);
    cudaGetSymbolAddress((void**)&p_ct_h, g_ct_h);
    cudaGetSymbolAddress((void**)&p_h_h,  g_h_h);
    cudaGetSymbolAddress((void**)&p_w1T,  g_w1T);
    cudaGetSymbolAddress((void**)&p_cw2T, g_cw2T);
    cudaGetSymbolAddress((void**)&p_tw2T, g_tw2T);
    cudaGetSymbolAddress((void**)&p_gwT,  g_gwT);
    cudaGetSymbolAddress((void**)&p_fftA, g_fftA);
    cudaGetSymbolAddress((void**)&p_irA,  g_irA);
    cudaGetSymbolAddress((void**)&p_BrT,  g_BrT);
    cudaGetSymbolAddress((void**)&p_BiT,  g_BiT);

    static int s_attr_done = 0;
    if (!s_attr_done) {
        cudaFuncSetAttribute(k_gemm_h, cudaFuncAttributeMaxDynamicSharedMemorySize,
                             SMEM_BYTES);
        s_attr_done = 1;
    }

    dim3 th(256);
    auto grid = [](int N, int M) { return dim3((N + 127) / 128, (M + 127) / 128); };

    // 0) tables + done reset
    k_init_tables<<<(SPATIAL * NF + 255) / 256, 256>>>();

    // 0b) weight transposes (pads stay zero)
    k_tr<<<dim3(3, 1028), th>>>(cw1, 514, F4, p_w1T, KW1, 0);
    k_tr<<<dim3(3, 1028), th>>>(cw1 + (size_t)514 * F4, 514, F4, p_w1T + 544, KW1, 0);
    k_tr<<<dim3(3, 1028), th>>>(tw1, 514, F4, p_w1T, KW1, 1028);
    k_tr<<<dim3(3, 1028), th>>>(tw1 + (size_t)514 * F4, 514, F4, p_w1T + 544, KW1, 1028);
    k_tr<<<dim3(5, 514), th>>>(cw2, F4, F2, p_cw2T, KW2, 0);
    k_tr<<<dim3(5, 514), th>>>(tw2, F4, F2, p_tw2T, KW2, 0);
    k_tr<<<dim3(3, 257), th>>>(dw1, F2, NF, p_gwT, KD, 0);
    k_tr<<<dim3(3, 128), th>>>(sw1, F2, FH, p_gwT, KD, 257);
    k_gbias<<<2, th>>>(db1, sb1);

    // 1) rfft: split inputs, merged split-fp16 GEMM [8192 x 514 x 1536]
    k_split_in<<<2 * ROWS, th>>>(carrier, traj);
    k_gemm_h<<<grid(F2, 2 * ROWS), th, SMEM_BYTES>>>(
        p_fftA, p_fftA, KFR, KFR / 32,
        p_BrT, p_BrT, KFR, 2 * ROWS,
        p_ct, F2, 2 * ROWS, F2, KFR / 32,
        nullptr, nullptr, nullptr, 0,
        p_ct_h, KD, 0, 0);

    // 2) per-batch constant base
    dim3 bg((F4 + 31) / 32, BSZ);
    k_base<<<bg, th>>>(srcp, tgtp, cw1, cb1, 0);
    k_base<<<bg, th>>>(srcp, tgtp, tw1, tb1, 1028);

    // 3) 20 fixed-point steps
    for (int s = 0; s < MAX_STEPS; s++) {
        // merged freq-net GEMM1: [4096 x 2056]
        k_gemm_h<<<grid(2056, ROWS), th, SMEM_BYTES>>>(
            p_ct_h, p_ct_h + (size_t)ROWS * KD, KD, 17,
            p_w1T, p_w1T, KW1, ROWS,
            p_h, 2056, ROWS, 2056, KW1 / 32,
            nullptr, nullptr, p_base, NBASE,
            nullptr, 0, 0, 1);
        // LN + GELU -> fp16 hidden (+ fct cols 512/513 tail)
        k_ln_gelu<<<dim3(ROWS, 2), th>>>(cg, cbe, tg_, tbe, cb2, tb2);
        // merged GEMM2: [8192 x 512] -> exactly one wave (256 CTAs)
        k_gemm_h<<<grid(512, 2 * ROWS), th, SMEM_BYTES>>>(
            p_h_h, p_h_h, KW2, KW2 / 32,
            p_cw2T, p_tw2T, KW2, ROWS,
            p_fct, F2, 2 * ROWS, 512, KW2 / 32,
            cb2, tb2, nullptr, 0,
            nullptr, 0, 2, 1);
        // merged gating GEMM: [8192 x 385] (as R10)
        k_gemm_h<<<grid(NG, 2 * ROWS), th, SMEM_BYTES>>>(
            p_ct_h, p_ct_h, KD, KD / 32,
            p_gwT, p_gwT, KD, 2 * ROWS,
            p_g, 512, 2 * ROWS, NG, KD / 32,
            p_gbias, p_gbias, nullptr, 0,
            nullptr, 0, 1, 1);
        // heads + update fused
        k_gate_update<<<ROWS, th>>>(fd, dw2, db2, sw2, sb2, csc, tsc);
        k_reduce_finalize<<<1, 1024>>>();
        k_apply<<<2 * ROWS, th>>>();
    }

    // 4) irfft: split state, merged split-fp16 GEMM [8192 x 512 x 1632]
    k_split_state<<<2 * ROWS, th>>>();
    k_gemm_h<<<grid(SPATIAL, 2 * ROWS), th, SMEM_BYTES>>>(
        p_irA, p_irA, KFI, KFI / 32,
        p_BiT, p_BiT, KFI, 2 * ROWS,
        out, SPATIAL, 2 * ROWS, SPATIAL, KFI / 32,
        nullptr, nullptr, nullptr, 0,
        nullptr, 0, 0, 0);
    (void)in_sizes; (void)n_in; (void)out_size;
}

// round 16
// speedup vs baseline: 1.4973x; 1.4973x over previous
#include <cuda_runtime.h>
#include <cuda_fp16.h>
#include <math.h>
#include <stdint.h>

// ---------------- problem constants ----------------
#define BSZ 8
#define SEQ 512
#define ROWS 4096          // BSZ*SEQ
#define SPATIAL 512
#define NF 257             // rfft bins
#define F2 514
#define F4 1028
#define FH 128
#define MAX_STEPS 20
#define TOLV 1e-3f
// padded GEMM dims
#define KW1 1088           // GEMM1 K: 2*544
#define NW1 2176
#define KW2 1056           // GEMM2 K
#define NW2 640
#define KD  544            // gating K / fp16 state row
#define NG  385            // gating N: 257 hd + 128 hs
#define NGP 512
#define NBASE 2176
// FFT split-fp16 GEMM dims
#define KFR 1536           // rfft K: 3*512
#define KFI 1632           // irfft K: 3*544
// GEMM smem: 4 stages x (A 128x40 + B 128x40) halfs
#define STAGE_H 10240
#define STAGE_B 20480
#define SMEM_BYTES (4 * STAGE_B)

// ---------------- device scratch (static, zero-initialized) ----------------
__device__ float g_ct[2 * ROWS * F2];      // fp32 state: rows 0..4095 c, 4096.. t
__device__ float g_new[2 * ROWS * F2];
__device__ float g_h[ROWS * 2056];         // merged GEMM1 output
__device__ float g_fct[2 * ROWS * F2];     // rows 0..4095 fc, 4096.. ft
__device__ float g_g[2 * ROWS * 512];      // gating hidden: cols 0..256 hd, 257..384 hs
__device__ float g_base[BSZ * NBASE];
__device__ float g_gbias[NGP];
__device__ float g_rn_c[ROWS], g_rn_t[ROWS], g_sq_c[ROWS], g_sq_t[ROWS];
__device__ float g_scal[4];
__device__ int   g_done;
// fp16 activations (pads never written -> stay zero)
__device__ __half g_ct_h[2 * ROWS * KD];
__device__ __half g_h_h[2 * ROWS * KW2];
// fp16 K-major weights (pads stay zero)
__device__ __half g_w1T[NW1 * KW1];
__device__ __half g_cw2T[NW2 * KW2];
__device__ __half g_tw2T[NW2 * KW2];
__device__ __half g_gwT[NGP * KD];
// split-fp16 FFT operands/tables
__device__ __half g_fftA[2 * ROWS * KFR];  // [x_hi | x_hi | x_lo]
__device__ __half g_irA[2 * ROWS * KFI];   // [s_hi | s_hi | s_lo]
__device__ __half g_BrT[640 * KFR];
__device__ __half g_BiT[512 * KFI];

// ---------------- helpers ----------------
__device__ __forceinline__ float gelu_f(float x) {
    return 0.5f * x * (1.0f + erff(x * 0.70710678118654752f));
}
__device__ __forceinline__ uint32_t smem_u32(const void* p) {
    uint32_t a;
    asm("{ .reg .u64 t; cvta.to.shared.u64 t, %1; cvt.u32.u64 %0, t; }" : "=r"(a) : "l"(p));
    return a;
}
__device__ __forceinline__ void cp16(uint32_t dst, const void* src) {
    asm volatile("cp.async.cg.shared.global [%0], [%1], 16;" :: "r"(dst), "l"(src));
}
__device__ __forceinline__ void ldm_x4(uint32_t* r, uint32_t addr) {
    asm volatile("ldmatrix.sync.aligned.m8n8.x4.shared.b16 {%0,%1,%2,%3}, [%4];"
                 : "=r"(r[0]), "=r"(r[1]), "=r"(r[2]), "=r"(r[3]) : "r"(addr));
}

// ---------------- table init: split-fp16 DFT tables ----------------
__global__ void k_init_tables() {
    int idx = blockIdx.x * blockDim.x + threadIdx.x;
    if (idx == 0) g_done = 0;
    int total = SPATIAL * NF;
    if (idx >= total) return;
    int n = idx / NF, q = idx % NF;
    double r = (double)((q * n) & 511) / 256.0;
    double sv, cv;
    sincospi(r, &sv, &cv);
    float cf = (float)cv, sf = (float)(-sv);
    __half chh = __float2half_rn(cf), shh = __float2half_rn(sf);
    __half cll = __float2half_rn(cf - __half2float(chh));
    __half sll = __float2half_rn(sf - __half2float(shh));
    __half* Rc = g_BrT + (size_t)(2 * q) * KFR;
    __half* Rs = g_BrT + (size_t)(2 * q + 1) * KFR;
    Rc[n] = chh; Rc[512 + n] = cll; Rc[1024 + n] = chh;
    Rs[n] = shh; Rs[512 + n] = sll; Rs[1024 + n] = shh;
    double w = (q == 0 || q == NF - 1) ? 1.0 : 2.0;
    float ic = (float)(w * cv / 512.0), is = (float)(-w * sv / 512.0);
    __half ich = __float2half_rn(ic), ish = __float2half_rn(is);
    __half icl = __float2half_rn(ic - __half2float(ich));
    __half isl = __float2half_rn(is - __half2float(ish));
    __half* Bn = g_BiT + (size_t)n * KFI;
    Bn[2 * q] = ich;        Bn[544 + 2 * q] = icl;        Bn[1088 + 2 * q] = ich;
    Bn[2 * q + 1] = ish;    Bn[544 + 2 * q + 1] = isl;    Bn[1088 + 2 * q + 1] = ish;
}

// ---------------- input split: carrier/traj -> [hi|hi|lo] fp16 ----------------
__global__ void k_split_in(const float* __restrict__ carrier, const float* __restrict__ traj) {
    int r = blockIdx.x, tid = threadIdx.x;
    const float* src = (r < ROWS) ? carrier + (size_t)r * SPATIAL
                                  : traj + (size_t)(r - ROWS) * SPATIAL;
    __half* d = g_fftA + (size_t)r * KFR;
    for (int k = tid; k < SPATIAL; k += 256) {
        float x = src[k];
        __half h = __float2half_rn(x);
        __half l = __float2half_rn(x - __half2float(h));
        d[k] = h; d[512 + k] = h; d[1024 + k] = l;
    }
}

// ---------------- state split for irfft ----------------
__global__ void k_split_state() {
    int r = blockIdx.x, tid = threadIdx.x;
    const float* src = g_ct + (size_t)r * F2;
    __half* d = g_irA + (size_t)r * KFI;
    for (int j = tid; j < F2; j += 256) {
        float x = src[j];
        __half h = __float2half_rn(x);
        __half l = __float2half_rn(x - __half2float(h));
        d[j] = h; d[544 + j] = h; d[1088 + j] = l;
    }
}

// ---------------- transpose W[k][n] -> WT[(n_off+n)*ldk + k] fp16 ----------------
__global__ void k_tr(const float* __restrict__ W, int K, int N,
                     __half* __restrict__ WT, int ldk, int n_off) {
    int k = blockIdx.x * 256 + threadIdx.x;
    int n = blockIdx.y;
    if (k >= K) return;
    WT[(size_t)(n_off + n) * ldk + k] = __float2half_rn(W[(size_t)k * N + n]);
}

// ---------------- gating bias concat ----------------
__global__ void k_gbias(const float* __restrict__ db1, const float* __restrict__ sb1) {
    int i = threadIdx.x + blockIdx.x * 256;
    if (i >= NGP) return;
    g_gbias[i] = (i < 257) ? db1[i] : (i < NG ? sb1[i - 257] : 0.f);
}

// =====================================================================
// FP16 tensor GEMM, 4-stage cp.async(16B) pipeline, ldmatrix fragments,
// one sync per K-block, 2 CTAs/SM.
// =====================================================================
__global__ __launch_bounds__(256, 2) void k_gemm_h(
    const __half* __restrict__ A_lo, const __half* __restrict__ A_hi,
    int ldaH, int kb_lo,
    const __half* __restrict__ B_lo, const __half* __restrict__ B_hi,
    int ldbH, int M_lo,
    float* __restrict__ C, int ldc, int M, int N, int nkb,
    const float* __restrict__ bias_lo, const float* __restrict__ bias_hi,
    const float* __restrict__ base, int base_ld,
    __half* __restrict__ Ch, int ldch,
    int act, int chk) {
    if (chk && g_done) return;
    extern __shared__ __half dyn[];

    const int tid = threadIdx.x;
    const int warp = tid >> 5, lane = tid & 31;
    const int gid = lane >> 2, tg = lane & 3;
    const int wm = warp & 1, wn = warp >> 1;
    const int row0 = blockIdx.y * 128, col0 = blockIdx.x * 128;

    const __half* BT = (row0 < M_lo) ? B_lo : B_hi;
    const float* bias = (row0 < M_lo) ? bias_lo : bias_hi;

    float acc[4][4][4];
#pragma unroll
    for (int mi = 0; mi < 4; mi++)
#pragma unroll
        for (int ni = 0; ni < 4; ni++)
#pragma unroll
            for (int q = 0; q < 4; q++) acc[mi][ni][q] = 0.f;

    const uint32_t sbase = smem_u32(dyn);
    const int rr2 = tid >> 2;
    const int c16 = tid & 3;

    auto issue = [&](int kb) {
        int buf = kb & 3;
        const __half* Ab;
        int kk;
        if (kb < kb_lo) { Ab = A_lo; kk = kb * 32; }
        else            { Ab = A_hi; kk = (kb - kb_lo) * 32; }
        uint32_t dA = sbase + buf * STAGE_B + rr2 * 80u + c16 * 16u;
        const __half* gA = Ab + (size_t)(row0 + rr2) * ldaH + kk + c16 * 8;
        cp16(dA, gA);
        cp16(dA + 64 * 80u, gA + (size_t)64 * ldaH);
        uint32_t dB = dA + 10240u;
        const __half* gB = BT + (size_t)(col0 + rr2) * ldbH + kb * 32 + c16 * 8;
        cp16(dB, gB);
        cp16(dB + 64 * 80u, gB + (size_t)64 * ldbH);
        asm volatile("cp.async.commit_group;" ::: "memory");
    };
    auto commit_empty = [&]() {
        asm volatile("cp.async.commit_group;" ::: "memory");
    };

    const uint32_t aRow = (uint32_t)(wm * 64 + (lane & 7) + ((lane & 8) ? 8 : 0));
    const uint32_t aColB = (lane & 16) ? 16u : 0u;
    const uint32_t bRow = (uint32_t)(wn * 32 + (lane & 7) + ((lane & 16) ? 8 : 0));
    const uint32_t bColB = (lane & 8) ? 16u : 0u;

    issue(0);
    if (nkb > 1) issue(1); else commit_empty();

    for (int kb = 0; kb < nkb; kb++) {
        if (kb + 2 < nkb) issue(kb + 2); else commit_empty();
        asm volatile("cp.async.wait_group 2;" ::: "memory");
        __syncthreads();
        int buf = kb & 3;
        uint32_t stA = sbase + buf * STAGE_B;
        uint32_t stB = stA + 10240u;
#pragma unroll
        for (int s = 0; s < 2; s++) {
            uint32_t af[4][4], bf[4][2];
#pragma unroll
            for (int mi = 0; mi < 4; mi++)
                ldm_x4(af[mi], stA + (aRow + mi * 16) * 80u + s * 32u + aColB);
#pragma unroll
            for (int nj = 0; nj < 2; nj++) {
                uint32_t r[4];
                ldm_x4(r, stB + (bRow + nj * 16) * 80u + s * 32u + bColB);
                bf[2 * nj][0] = r[0]; bf[2 * nj][1] = r[1];
                bf[2 * nj + 1][0] = r[2]; bf[2 * nj + 1][1] = r[3];
            }
#pragma unroll
            for (int mi = 0; mi < 4; mi++)
#pragma unroll
                for (int ni = 0; ni < 4; ni++) {
                    asm volatile(
                        "mma.sync.aligned.m16n8k16.row.col.f32.f16.f16.f32 "
                        "{%0,%1,%2,%3}, {%4,%5,%6,%7}, {%8,%9}, {%0,%1,%2,%3};"
                        : "+f"(acc[mi][ni][0]), "+f"(acc[mi][ni][1]),
                          "+f"(acc[mi][ni][2]), "+f"(acc[mi][ni][3])
                        : "r"(af[mi][0]), "r"(af[mi][1]), "r"(af[mi][2]), "r"(af[mi][3]),
                          "r"(bf[ni][0]), "r"(bf[ni][1]));
                }
        }
    }

    // epilogue
#pragma unroll
    for (int mi = 0; mi < 4; mi++) {
#pragma unroll
        for (int ni = 0; ni < 4; ni++) {
#pragma unroll
            for (int q = 0; q < 4; q++) {
                int r = row0 + wm * 64 + mi * 16 + gid + (q >> 1) * 8;
                int c = col0 + wn * 32 + ni * 8 + tg * 2 + (q & 1);
                if (r >= M || c >= N) continue;
                float v = acc[mi][ni][q];
                if (bias) v += bias[c];
                if (base) v += base[(r >> 9) * base_ld + c];
                if (act == 1) v = gelu_f(v);
                else if (act == 2) v = tanhf(v);
                C[(size_t)r * ldc + c] = v;
                if (Ch) Ch[(size_t)r * ldch + c] = __float2half_rn(v);
            }
        }
    }
}

// ---------------- per-batch constant base ----------------
__global__ void k_base(const float* __restrict__ src, const float* __restrict__ tgt,
                       const float* __restrict__ w1, const float* __restrict__ b1,
                       int out_off) {
    int b = blockIdx.y;
    int tid = threadIdx.x;
    int jj = tid & 31;
    int ks = tid >> 5;
    int j = blockIdx.x * 32 + jj;
    float s = 0.f;
    if (j < F4) {
        const float* ps = src + b * 513;
        const float* pt = tgt + b * 513;
        for (int k = ks * 128; k < ks * 128 + 128; k++) {
            float x = (k < 512) ? ps[k] : pt[k - 512];
            s = fmaf(x, w1[(size_t)(F4 + k) * F4 + j], s);
        }
    }
    __shared__ float sh[8][32];
    sh[ks][jj] = s;
    __syncthreads();
    if (ks == 0 && j < F4) {
        float t = b1[j];
#pragma unroll
        for (int q = 0; q < 8; q++) t += sh[q][jj];
        g_base[b * NBASE + out_off + j] = t;
    }
}

// ---------------- LayerNorm + exact GELU -> fp16 hidden ----------------
__global__ void k_ln_gelu(const float* __restrict__ gc, const float* __restrict__ bc,
                          const float* __restrict__ gt, const float* __restrict__ bt) {
    if (g_done) return;
    int r = blockIdx.x, h = blockIdx.y, tid = threadIdx.x;
    const float* g = h ? gt : gc;
    const float* be = h ? bt : bc;
    const float4* hr = (const float4*)(g_h + (size_t)r * 2056 + h * 1028);
    __half2* out = (__half2*)(g_h_h + (size_t)(h * ROWS + r) * KW2);
    float s = 0.f, s2 = 0.f;
    for (int j = tid; j < 257; j += 256) {
        float4 x = hr[j];
        s += x.x + x.y + x.z + x.w;
        s2 += x.x * x.x + x.y * x.y + x.z * x.z + x.w * x.w;
    }
    __shared__ float sa[256], sb[256];
    sa[tid] = s; sb[tid] = s2;
    __syncthreads();
    for (int o = 128; o > 0; o >>= 1) {
        if (tid < o) { sa[tid] += sa[tid + o]; sb[tid] += sb[tid + o]; }
        __syncthreads();
    }
    float mean = sa[0] / F4;
    float var = sb[0] / F4 - mean * mean;
    float rs = rsqrtf(var + 1e-5f);
    const float4* g4 = (const float4*)g;
    const float4* b4 = (const float4*)be;
    for (int j = tid; j < 257; j += 256) {
        float4 x = hr[j], gg = g4[j], bb = b4[j];
        float2 lo, hi;
        lo.x = gelu_f((x.x - mean) * rs * gg.x + bb.x);
        lo.y = gelu_f((x.y - mean) * rs * gg.y + bb.y);
        hi.x = gelu_f((x.z - mean) * rs * gg.z + bb.z);
        hi.y = gelu_f((x.w - mean) * rs * gg.w + bb.w);
        out[2 * j] = __float22half2_rn(lo);
        out[2 * j + 1] = __float22half2_rn(hi);
    }
}

// ---------------- fused heads + update ----------------
__global__ void k_gate_update(const float* __restrict__ fd,
                              const float* __restrict__ dw2, const float* __restrict__ db2,
                              const float* __restrict__ sw2, const float* __restrict__ sb2,
                              const float* __restrict__ cs_p, const float* __restrict__ ts_p) {
    if (g_done) return;
    int row = blockIdx.x, tid = threadIdx.x;
    const float* gc = g_g + (size_t)row * 512;
    const float* gt = g_g + (size_t)(ROWS + row) * 512;
    float s1 = 0.f, s2 = 0.f, s3 = 0.f;
    for (int k = tid; k < 257; k += 256) {
        float w = dw2[k];
        s1 = fmaf(gc[k], w, s1);
        s2 = fmaf(gt[k], w, s2);
    }
    if (tid < 128) s3 = gc[257 + tid] * sw2[tid];
    __shared__ float h1[256], h2[256], h3[256];
    h1[tid] = s1; h2[tid] = s2; h3[tid] = s3;
    __syncthreads();
    for (int o = 128; o > 0; o >>= 1) {
        if (tid < o) { h1[tid] += h1[tid + o]; h2[tid] += h2[tid + o]; h3[tid] += h3[tid + o]; }
        __syncthreads();
    }
    __shared__ float sh_ac, sh_at;
    if (tid == 0) {
        float a_c = 1.f / (1.f + expf(-(h1[0] + db2[0])));
        float a_t = 1.f / (1.f + expf(-(h2[0] + db2[0])));
        if (isnan(a_c)) a_c = 0.f;
        if (isnan(a_t)) a_t = 0.f;
        float gam = 1.f / (1.f + expf(-(h3[0] + sb2[0]))) + 0.5f;
        sh_ac = gam * a_c * (*cs_p);
        sh_at = gam * a_t * (*ts_p);
    }
    __syncthreads();
    float ac = sh_ac, at = sh_at;

    const float2* ct_c = (const float2*)(g_ct + (size_t)row * F2);
    const float2* ct_t = (const float2*)(g_ct + (size_t)(ROWS + row) * F2);
    const float2* fc2 = (const float2*)(g_fct + (size_t)row * F2);
    const float2* ft2 = (const float2*)(g_fct + (size_t)(ROWS + row) * F2);
    float2* nw_c = (float2*)(g_new + (size_t)row * F2);
    float2* nw_t = (float2*)(g_new + (size_t)(ROWS + row) * F2);
    float dc2 = 0.f, dt2 = 0.f, sc2 = 0.f, st2 = 0.f;
    for (int j2 = tid; j2 < 257; j2 += 256) {
        int j = 2 * j2;
        float fd0 = fd[j < NF ? j : j - NF];
        float fd1 = fd[(j + 1) < NF ? (j + 1) : (j + 1 - NF)];
        float2 c = ct_c[j2], f = fc2[j2];
        float2 nc;
        nc.x = fmaf(fd0, c.x, ac * f.x);
        nc.y = fmaf(fd1, c.y, ac * f.y);
        nw_c[j2] = nc;
        float d0 = nc.x - c.x, d1 = nc.y - c.y;
        dc2 += d0 * d0 + d1 * d1; sc2 += nc.x * nc.x + nc.y * nc.y;
        float2 t = ct_t[j2], ff = ft2[j2];
        float2 nt;
        nt.x = fmaf(fd0, t.x, at * ff.x);
        nt.y = fmaf(fd1, t.y, at * ff.y);
        nw_t[j2] = nt;
        d0 = nt.x - t.x; d1 = nt.y - t.y;
        dt2 += d0 * d0 + d1 * d1; st2 += nt.x * nt.x + nt.y * nt.y;
    }
    h1[tid] = dc2; h2[tid] = dt2; h3[tid] = sc2;
    __shared__ float h4[256];
    h4[tid] = st2;
    __syncthreads();
    for (int o = 128; o > 0; o >>= 1) {
        if (tid < o) { h1[tid] += h1[tid + o]; h2[tid] += h2[tid + o];
                       h3[tid] += h3[tid + o]; h4[tid] += h4[tid + o]; }
        __syncthreads();
    }
    if (tid == 0) {
        g_rn_c[row] = sqrtf(h1[0]);
        g_rn_t[row] = sqrtf(h2[0]);
        g_sq_c[row] = h3[0];
        g_sq_t[row] = h4[0];
    }
}

// ---------------- reduce + convergence decision ----------------
__global__ void k_reduce_finalize() {
    __shared__ float4 sh[1024];
    int tid = threadIdx.x;
    float4 a = make_float4(0.f, 0.f, 0.f, 0.f);
    for (int i = tid; i < ROWS; i += 1024) {
        a.x += g_rn_c[i]; a.y += g_rn_t[i]; a.z += g_sq_c[i]; a.w += g_sq_t[i];
    }
    sh[tid] = a;
    __syncthreads();
    for (int o = 512; o > 0; o >>= 1) {
        if (tid < o) {
            sh[tid].x += sh[tid + o].x; sh[tid].y += sh[tid + o].y;
            sh[tid].z += sh[tid + o].z; sh[tid].w += sh[tid + o].w;
        }
        __syncthreads();
    }
    if (tid == 0) {
        if (g_done) {
            g_scal[2] = 0.f;
        } else {
            float dc = sh[0].x / (float)ROWS;
            float dt = sh[0].y / (float)ROWS;
            float nc = sqrtf(sh[0].z);
            float nt = sqrtf(sh[0].w);
            int conv = (dc < TOLV) && (dt < TOLV);
            g_scal[0] = conv ? 1.f : (nc > 10.f ? 10.f / nc : 1.f);
            g_scal[1] = conv ? 1.f : (nt > 10.f ? 10.f / nt : 1.f);
            g_scal[2] = 1.f;
            if (conv) g_done = 1;
        }
    }
}

// ---------------- apply: commit state (fp32 + fp16) ----------------
__global__ void k_apply() {
    if (g_scal[2] == 0.f) return;
    int r = blockIdx.x, tid = threadIdx.x;
    float sc = (r < ROWS) ? g_scal[0] : g_scal[1];
    const float2* nw = (const float2*)(g_new + (size_t)r * F2);
    float2* ct = (float2*)(g_ct + (size_t)r * F2);
    __half2* hh = (__half2*)(g_ct_h + (size_t)r * KD);
    for (int j = tid; j < 257; j += 256) {
        float2 v = nw[j];
        v.x *= sc; v.y *= sc;
        ct[j] = v;
        hh[j] = __float22half2_rn(v);
    }
}

// ---------------- host launch ----------------
extern "C" void kernel_launch(void* const* d_in, const int* in_sizes, int n_in,
                              void* d_out, int out_size) {
    const float* carrier = (const float*)d_in[0];
    const float* traj    = (const float*)d_in[1];
    const float* srcp    = (const float*)d_in[2];
    const float* tgtp    = (const float*)d_in[3];
    const float* cw1 = (const float*)d_in[4];
    const float* cb1 = (const float*)d_in[5];
    const float* cg  = (const float*)d_in[6];
    const float* cbe = (const float*)d_in[7];
    const float* cw2 = (const float*)d_in[8];
    const float* cb2 = (const float*)d_in[9];
    const float* tw1 = (const float*)d_in[10];
    const float* tb1 = (const float*)d_in[11];
    const float* tg_ = (const float*)d_in[12];
    const float* tbe = (const float*)d_in[13];
    const float* tw2 = (const float*)d_in[14];
    const float* tb2 = (const float*)d_in[15];
    const float* fd  = (const float*)d_in[16];
    const float* dw1 = (const float*)d_in[17];
    const float* db1 = (const float*)d_in[18];
    const float* dw2 = (const float*)d_in[19];
    const float* db2 = (const float*)d_in[20];
    const float* sw1 = (const float*)d_in[21];
    const float* sb1 = (const float*)d_in[22];
    const float* sw2 = (const float*)d_in[23];
    const float* sb2 = (const float*)d_in[24];
    const float* csc = (const float*)d_in[25];
    const float* tsc = (const float*)d_in[26];
    float* out = (float*)d_out;

    float *p_ct, *p_h, *p_fct, *p_g, *p_base, *p_gbias;
    __half *p_ct_h, *p_h_h, *p_w1T, *p_cw2T, *p_tw2T, *p_gwT;
    __half *p_fftA, *p_irA, *p_BrT, *p_BiT;
    cudaGetSymbolAddress((void**)&p_ct,   g_ct);
    cudaGetSymbolAddress((void**)&p_h,    g_h);
    cudaGetSymbolAddress((void**)&p_fct,  g_fct);
    cudaGetSymbolAddress((void**)&p_g,    g_g);
    cudaGetSymbolAddress((void**)&p_base, g_base);
    cudaGetSymbolAddress((void**)&p_gbias,g_gbias);
    cudaGetSymbolAddress((void**)&p_ct_h, g_ct_h);
    cudaGetSymbolAddress((void**)&p_h_h,  g_h_h);
    cudaGetSymbolAddress((void**)&p_w1T,  g_w1T);
    cudaGetSymbolAddress((void**)&p_cw2T, g_cw2T);
    cudaGetSymbolAddress((void**)&p_tw2T, g_tw2T);
    cudaGetSymbolAddress((void**)&p_gwT,  g_gwT);
    cudaGetSymbolAddress((void**)&p_fftA, g_fftA);
    cudaGetSymbolAddress((void**)&p_irA,  g_irA);
    cudaGetSymbolAddress((void**)&p_BrT,  g_BrT);
    cudaGetSymbolAddress((void**)&p_BiT,  g_BiT);

    static int s_attr_done = 0;
    if (!s_attr_done) {
        cudaFuncSetAttribute(k_gemm_h, cudaFuncAttributeMaxDynamicSharedMemorySize,
                             SMEM_BYTES);
        s_attr_done = 1;
    }

    dim3 th(256);
    auto grid = [](int N, int M) { return dim3((N + 127) / 128, (M + 127) / 128); };

    // 0) tables + done reset
    k_init_tables<<<(SPATIAL * NF + 255) / 256, 256>>>();

    // 0b) weight transposes (pads stay zero)
    k_tr<<<dim3(3, 1028), th>>>(cw1, 514, F4, p_w1T, KW1, 0);
    k_tr<<<dim3(3, 1028), th>>>(cw1 + (size_t)514 * F4, 514, F4, p_w1T + 544, KW1, 0);
    k_tr<<<dim3(3, 1028), th>>>(tw1, 514, F4, p_w1T, KW1, 1028);
    k_tr<<<dim3(3, 1028), th>>>(tw1 + (size_t)514 * F4, 514, F4, p_w1T + 544, KW1, 1028);
    k_tr<<<dim3(5, 514), th>>>(cw2, F4, F2, p_cw2T, KW2, 0);
    k_tr<<<dim3(5, 514), th>>>(tw2, F4, F2, p_tw2T, KW2, 0);
    k_tr<<<dim3(3, 257), th>>>(dw1, F2, NF, p_gwT, KD, 0);
    k_tr<<<dim3(3, 128), th>>>(sw1, F2, FH, p_gwT, KD, 257);
    k_gbias<<<2, th>>>(db1, sb1);

    // 1) rfft: split inputs, one merged split-fp16 GEMM [8192 x 514 x 1536]
    k_split_in<<<2 * ROWS, th>>>(carrier, traj);
    k_gemm_h<<<grid(F2, 2 * ROWS), th, SMEM_BYTES>>>(
        p_fftA, p_fftA, KFR, KFR / 32,
        p_BrT, p_BrT, KFR, 2 * ROWS,
        p_ct, F2, 2 * ROWS, F2, KFR / 32,
        nullptr, nullptr, nullptr, 0,
        p_ct_h, KD, 0, 0);

    // 2) per-batch constant base
    dim3 bg((F4 + 31) / 32, BSZ);
    k_base<<<bg, th>>>(srcp, tgtp, cw1, cb1, 0);
    k_base<<<bg, th>>>(srcp, tgtp, tw1, tb1, 1028);

    // 3) 20 fixed-point steps
    for (int s = 0; s < MAX_STEPS; s++) {
        // merged freq-net GEMM1: [4096 x 2056]
        k_gemm_h<<<grid(2056, ROWS), th, SMEM_BYTES>>>(
            p_ct_h, p_ct_h + (size_t)ROWS * KD, KD, 17,
            p_w1T, p_w1T, KW1, ROWS,
            p_h, 2056, ROWS, 2056, KW1 / 32,
            nullptr, nullptr, p_base, NBASE,
            nullptr, 0, 0, 1);
        // LN + GELU -> fp16 hidden
        k_ln_gelu<<<dim3(ROWS, 2), th>>>(cg, cbe, tg_, tbe);
        // merged GEMM2: [8192 x 514]
        k_gemm_h<<<grid(F2, 2 * ROWS), th, SMEM_BYTES>>>(
            p_h_h, p_h_h, KW2, KW2 / 32,
            p_cw2T, p_tw2T, KW2, ROWS,
            p_fct, F2, 2 * ROWS, F2, KW2 / 32,
            cb2, tb2, nullptr, 0,
            nullptr, 0, 2, 1);
        // merged gating GEMM: [8192 x 385]
        k_gemm_h<<<grid(NG, 2 * ROWS), th, SMEM_BYTES>>>(
            p_ct_h, p_ct_h, KD, KD / 32,
            p_gwT, p_gwT, KD, 2 * ROWS,
            p_g, 512, 2 * ROWS, NG, KD / 32,
            p_gbias, p_gbias, nullptr, 0,
            nullptr, 0, 1, 1);
        // heads + update fused
        k_gate_update<<<ROWS, th>>>(fd, dw2, db2, sw2, sb2, csc, tsc);
        k_reduce_finalize<<<1, 1024>>>();
        k_apply<<<2 * ROWS, th>>>();
    }

    // 4) irfft: split state, one merged split-fp16 GEMM [8192 x 512 x 1632]
    k_split_state<<<2 * ROWS, th>>>();
    k_gemm_h<<<grid(SPATIAL, 2 * ROWS), th, SMEM_BYTES>>>(
        p_irA, p_irA, KFI, KFI / 32,
        p_BiT, p_BiT, KFI, 2 * ROWS,
        out, SPATIAL, 2 * ROWS, SPATIAL, KFI / 32,
        nullptr, nullptr, nullptr, 0,
        nullptr, 0, 0, 0);
    (void)in_sizes; (void)n_in; (void)out_size;
}